// round 4
// baseline (speedup 1.0000x reference)
#include <cuda_runtime.h>

#define BB 8
#define CC 32
#define FF 8
#define HH 128
#define WW 128
#define IHP 129
#define IWP 132                       // padded row stride (floats), 528 B
#define DSTR 132

#define A_SMEM_FLOATS (IHP*IWP + 16*IWP)   // I + stripe-offset table = 19140 -> 76560 B
#define B_SMEM_FLOATS (IHP*IWP + 8*DSTR)   // I + per-warp Drow       = 18084 -> 72336 B

// Global integral scratch: (256, 129, 132) f32 = 17.4 MB (L2-resident)
__device__ __align__(256) float g_I[BB * CC * IHP * IWP];

// ---------------------------------------------------------------------------
// Kernel A: build padded integral image per (b,c) in smem, write to g_I.
// 512 threads = 16 warps. 2-level column scan (8-row stripes).
// ---------------------------------------------------------------------------
__global__ void __launch_bounds__(512) build_integral(const float* __restrict__ in)
{
    extern __shared__ float sm[];
    float* I = sm;                      // [IHP][IWP]
    float* O = sm + IHP * IWP;          // [16][IWP] stripe offsets

    const int bc   = blockIdx.x;
    const int tid  = threadIdx.x;
    const int wid  = tid >> 5;
    const int lane = tid & 31;

    // Row 0 = 0
    if (tid < IWP) I[tid] = 0.0f;

    // ---- Row exclusive scans: warp w handles rows [8w .. 8w+7] ------------
    const float* img = in + (size_t)bc * (HH * WW);
#pragma unroll
    for (int r = 0; r < 8; ++r) {
        int row = wid * 8 + r;
        float4 c = *(const float4*)(img + (size_t)row * WW + 4 * lane);
        float s4 = c.x + c.y + c.z + c.w;
        float x = __shfl_up_sync(0xffffffffu, s4, 1);
        if (lane == 0) x = 0.0f;
#pragma unroll
        for (int off = 1; off < 32; off <<= 1) {
            float t = __shfl_up_sync(0xffffffffu, x, off);
            if (lane >= off) x += t;
        }
        float4 o;
        o.x = x;
        o.y = x + c.x;
        o.z = o.y + c.y;
        o.w = o.z + c.z;
        float* dst = I + (size_t)(row + 1) * IWP;
        *(float4*)(dst + 4 * lane) = o;            // cols 0..127
        if (lane == 31) {
            dst[128] = o.w + c.w;                  // col 128 = row total
            dst[129] = 0.0f; dst[130] = 0.0f; dst[131] = 0.0f;  // keep padding clean
        }
    }
    __syncthreads();

    // ---- Column scan, level 1: within-stripe inclusive sums ----------------
    // Warp w owns rows [8w+1 .. 8w+8]; lane covers float4 col-groups g, g=lane
    // plus lane 0 also handles group 32 (cols 128..131).
    for (int g = lane; g < 33; g += 32) {
        float* col = I + 4 * g + (size_t)(8 * wid + 1) * IWP;
        float4 s = make_float4(0.f, 0.f, 0.f, 0.f);
#pragma unroll
        for (int r = 0; r < 8; ++r) {
            float4 v = *(float4*)(col + (size_t)r * IWP);
            s.x += v.x; s.y += v.y; s.z += v.z; s.w += v.w;
            *(float4*)(col + (size_t)r * IWP) = s;
        }
    }
    __syncthreads();

    // ---- Column scan, level 2: exclusive prefix of stripe totals -----------
    if (tid < IWP) {
        float off = 0.0f;
        float* col = I + tid;
        float* ocol = O + tid;
#pragma unroll
        for (int s = 0; s < 16; ++s) {
            ocol[s * IWP] = off;
            off += col[(size_t)(8 * s + 8) * IWP];
        }
    }
    __syncthreads();

    // ---- Column scan, level 3: add stripe offsets ---------------------------
    for (int g = lane; g < 33; g += 32) {
        float4 o4 = *(float4*)(O + wid * IWP + 4 * g);
        float* col = I + 4 * g + (size_t)(8 * wid + 1) * IWP;
#pragma unroll
        for (int r = 0; r < 8; ++r) {
            float4 v = *(float4*)(col + (size_t)r * IWP);
            v.x += o4.x; v.y += o4.y; v.z += o4.z; v.w += o4.w;
            *(float4*)(col + (size_t)r * IWP) = v;
        }
    }
    __syncthreads();

    // ---- Write integral to global (coalesced float4) -----------------------
    float4* dst = (float4*)(g_I + (size_t)bc * (IHP * IWP));
    const float4* src = (const float4*)I;
    const int n4 = (IHP * IWP) / 4;                // 4257
    for (int i = tid; i < n4; i += 512) dst[i] = src[i];
}

// ---------------------------------------------------------------------------
// Kernel B: block = (h-quarter, bc). Copy integral L2->smem, then warp f
// computes 32 output rows with rolling register window.
// ---------------------------------------------------------------------------
__global__ void __launch_bounds__(256) boxconv_main(
    const float* __restrict__ xmn, const float* __restrict__ xmx,
    const float* __restrict__ ymn, const float* __restrict__ ymx,
    float* __restrict__ out)
{
    extern __shared__ float sm[];
    float* I = sm;                                  // [IHP][IWP]

    const int quarter = blockIdx.x;
    const int bc   = blockIdx.y;
    const int tid  = threadIdx.x;
    const int wid  = tid >> 5;
    const int lane = tid & 31;

    // ---- Copy integral image into smem -------------------------------------
    {
        const float4* src = (const float4*)(g_I + (size_t)bc * (IHP * IWP));
        float4* dst = (float4*)I;
        const int n4 = (IHP * IWP) / 4;             // 4257
#pragma unroll 5
        for (int i = tid; i < n4; i += 256) dst[i] = src[i];
    }
    __syncthreads();

    // ---- Phase C: warp = f, 32 h rows ---------------------------------------
    const int f  = wid;
    const int cf = (bc % CC) * FF + f;
    const float Hf = 128.0f, Wf = 128.0f;

    const float xm = __ldg(&xmn[cf]) * Hf;
    const float xM = __ldg(&xmx[cf]) * Hf;
    const float ym = __ldg(&ymn[cf]) * Wf;
    const float yM = __ldg(&ymx[cf]) * Wf;

    // Column-interp params: h-invariant, once per lane.
    int   j0[4], j1[4];
    float b0[4], b1[4];
#pragma unroll
    for (int k = 0; k < 4; ++k) {
        float wv = (float)(lane + 32 * k);
        float v0 = fminf(fmaxf(wv + ym, 0.0f), Wf);
        float v1 = fminf(fmaxf(wv + yM + 1.0f, 0.0f), Wf);
        float j0f = fminf(floorf(v0), Wf - 1.0f);
        float j1f = fminf(floorf(v1), Wf - 1.0f);
        b0[k] = v0 - j0f;
        b1[k] = v1 - j1f;
        j0[k] = (int)j0f;
        j1[k] = (int)j1f;
    }

    float* D = sm + IHP * IWP + wid * DSTR;
    float* outBase = out + ((size_t)(bc * FF + f) * HH) * WW;
    const int h0 = quarter * 32;

    float4 p0, q0, p1, q1;                          // rows i0, i0+1, i1, i1+1
    float e00 = 0.f, e01 = 0.f, e10 = 0.f, e11 = 0.f;
    int pi0 = -2, pi1 = -2;

    for (int hh = 0; hh < 32; ++hh) {
        const int h = h0 + hh;

        float u0 = fminf(fmaxf((float)h + xm, 0.0f), Hf);
        float u1 = fminf(fmaxf((float)h + xM + 1.0f, 0.0f), Hf);
        float i0f = fminf(floorf(u0), Hf - 1.0f);
        float i1f = fminf(floorf(u1), Hf - 1.0f);
        float a0 = u0 - i0f;
        float a1 = u1 - i1f;
        int i0 = (int)i0f;
        int i1 = (int)i1f;

        if (i0 != pi0) {
            const float* base = I + (size_t)i0 * IWP;
            if (i0 == pi0 + 1) { p0 = q0; e00 = e01; }
            else { p0 = *(const float4*)(base + 4 * lane); e00 = base[128]; }
            q0 = *(const float4*)(base + IWP + 4 * lane); e01 = base[IWP + 128];
            pi0 = i0;
        }
        if (i1 != pi1) {
            const float* base = I + (size_t)i1 * IWP;
            if (i1 == pi1 + 1) { p1 = q1; e10 = e11; }
            else { p1 = *(const float4*)(base + 4 * lane); e10 = base[128]; }
            q1 = *(const float4*)(base + IWP + 4 * lane); e11 = base[IWP + 128];
            pi1 = i1;
        }

        float4 d;
        d.x = (p1.x + a1 * (q1.x - p1.x)) - (p0.x + a0 * (q0.x - p0.x));
        d.y = (p1.y + a1 * (q1.y - p1.y)) - (p0.y + a0 * (q0.y - p0.y));
        d.z = (p1.z + a1 * (q1.z - p1.z)) - (p0.z + a0 * (q0.z - p0.z));
        d.w = (p1.w + a1 * (q1.w - p1.w)) - (p0.w + a0 * (q0.w - p0.w));
        *(float4*)(D + 4 * lane) = d;
        if (lane == 0)
            D[128] = (e10 + a1 * (e11 - e10)) - (e00 + a0 * (e01 - e00));
        __syncwarp();

        float* orow = outBase + (size_t)h * WW + lane;
#pragma unroll
        for (int k = 0; k < 4; ++k) {
            float d00 = D[j0[k]], d01 = D[j0[k] + 1];
            float d10 = D[j1[k]], d11 = D[j1[k] + 1];
            orow[32 * k] = (d10 + b1[k] * (d11 - d10))
                         - (d00 + b0[k] * (d01 - d00));
        }
        __syncwarp();
    }
}

// ---------------------------------------------------------------------------
extern "C" void kernel_launch(void* const* d_in, const int* in_sizes, int n_in,
                              void* d_out, int out_size) {
    const float* input = (const float*)d_in[0];
    const float* x_min = (const float*)d_in[1];
    const float* x_max = (const float*)d_in[2];
    const float* y_min = (const float*)d_in[3];
    const float* y_max = (const float*)d_in[4];
    float* out = (float*)d_out;

    static int configured = 0;
    const int a_smem = A_SMEM_FLOATS * sizeof(float);   // 76560 B
    const int b_smem = B_SMEM_FLOATS * sizeof(float);   // 72336 B
    if (!configured) {
        cudaFuncSetAttribute(build_integral,
                             cudaFuncAttributeMaxDynamicSharedMemorySize, a_smem);
        cudaFuncSetAttribute(boxconv_main,
                             cudaFuncAttributeMaxDynamicSharedMemorySize, b_smem);
        configured = 1;
    }

    build_integral<<<BB * CC, 512, a_smem>>>(input);

    dim3 grid(4, BB * CC);    // (h-quarter, bc)
    boxconv_main<<<grid, 256, b_smem>>>(x_min, x_max, y_min, y_max, out);
}